// round 13
// baseline (speedup 1.0000x reference)
#include <cuda_runtime.h>
#include <cstdint>

#define NCTA     125
#define ROWS     16
#define NTHREADS 256         // 8 warps; warp w reads h cols [256w, 256w+256)
#define RDIM     2000
#define XDIM     28
#define TSTEPS   28
#define BATCH    512
#define NSTEP    (BATCH*TSTEPS)
#define ODIM     10

// Static device scratch (zero-initialized; reset_kernel restores for next replay)
__device__ __align__(16) float g_h[2][2048];   // double-buffered hidden state
__device__ float    g_hlast[BATCH*RDIM];       // h at t = T-1 per batch element
__device__ unsigned g_ctr[32];                 // single global counter (padded line)

// ---- packed f32x2 helpers ----
__device__ __forceinline__ unsigned long long fma2(unsigned long long a,
                                                   unsigned long long b,
                                                   unsigned long long c) {
    unsigned long long d;
    asm("fma.rn.f32x2 %0, %1, %2, %3;" : "=l"(d) : "l"(a), "l"(b), "l"(c));
    return d;
}
__device__ __forceinline__ unsigned long long mul2(unsigned long long a,
                                                   unsigned long long b) {
    unsigned long long d;
    asm("mul.rn.f32x2 %0, %1, %2;" : "=l"(d) : "l"(a), "l"(b));
    return d;
}
__device__ __forceinline__ unsigned long long pk2(float lo, float hi) {
    unsigned long long u;
    asm("mov.b64 %0, {%1, %2};" : "=l"(u)
        : "r"(__float_as_uint(lo)), "r"(__float_as_uint(hi)));
    return u;
}
__device__ __forceinline__ float lo32(unsigned long long v) { return __uint_as_float((unsigned)v); }
__device__ __forceinline__ float hi32(unsigned long long v) { return __uint_as_float((unsigned)(v >> 32)); }

__device__ __forceinline__ unsigned ldrlx(const unsigned* p) {
    unsigned v;
    asm volatile("ld.relaxed.gpu.u32 %0, [%1];" : "=r"(v) : "l"(p) : "memory");
    return v;
}

// Min-phase gate: interleave SMEM flag checks inside the RT shadow of the
// in-flight global sample. First detector sets the flag; siblings see it in
// ~30-60 cyc instead of waiting out their own sampling phase (max->min).
// Returns a token the h-load addresses are made to depend on.
__device__ __forceinline__ unsigned gate_wait(const unsigned* cp, unsigned tgt,
                                              volatile unsigned* fl) {
    unsigned v = ldrlx(cp);
    if (v >= tgt) { *fl = 1u; return v; }
    for (;;) {
#pragma unroll
        for (int k = 0; k < 14; ++k) {          // ~14 x 30cyc LDS ~= one RT
            const unsigned f = *fl;
            if (f) return f + v;                 // token depends on flag
        }
        if (v >= tgt) break;                     // consume in-flight sample
        v = ldrlx(cp);                           // reissue (relaxed, 1 sector)
    }
    *fl = 1u;
    return v;
}

// Fast tanh: (e^{2x}-1)/(e^{2x}+1) via MUFU.EX2 + MUFU.RCP.
// Abs error ~1e-7 (same order as fp32 rounding); clamp kills overflow.
__device__ __forceinline__ float ftanh(float s) {
    s = fminf(fmaxf(s, -20.0f), 20.0f);
    float e;
    asm("ex2.approx.f32 %0, %1;" : "=f"(e) : "f"(s * 2.885390082f)); // 2/ln2... 2*log2(e)
    float r;
    asm("rcp.approx.f32 %0, %1;" : "=f"(r) : "f"(e + 1.0f));
    return (e - 1.0f) * r;
}

// W_ext element: [W_res | W_in | 0-pad], row r, extended column c
__device__ __forceinline__ float wext(const float* __restrict__ Wres,
                                      const float* __restrict__ Win,
                                      int r, int c) {
    if (c < RDIM)        return Wres[r * RDIM + c];
    if (c < RDIM + XDIM) return Win[r * XDIM + (c - RDIM)];
    return 0.0f;
}

// R1-validated register reduce-scatter stage
template <int M, int HALF>
__device__ __forceinline__ void rs_stage(float* a, int l) {
    const bool up = (l & M) != 0;
#pragma unroll
    for (int i = 0; i < HALF; ++i) {
        float send = up ? a[i] : a[i + HALF];
        float recv = __shfl_xor_sync(0xffffffffu, send, M);
        a[i] = (up ? a[i + HALF] : a[i]) + recv;
    }
}

__global__ void __launch_bounds__(NTHREADS, 1)
rnn_kernel(const float* __restrict__ x,
           const float* __restrict__ W_in,
           const float* __restrict__ W_res) {
    __shared__ float spart[2][8][ROWS];     // parity double-buffered partials
    __shared__ volatile unsigned sflag[2];  // parity detection flags

    const int tid   = threadIdx.x;
    const int w     = tid >> 5;
    const int l     = tid & 31;
    const int rbase = blockIdx.x * ROWS;
    const int c0    = w * 256 + l * 4;          // lane's column base (R1 layout)
    unsigned tgt = 0u;                           // poll target = s * NCTA

    const bool xlane = (w == 7) && (l >= 20) && (l < 27);  // cols 2000..2027 <- x
    const bool zlane = (w == 7) && (l >= 27);              // cols 2028..2047 <- 0

    if (tid < 2) sflag[tid] = 0u;   // drained by step-0's barrier (gate at s=0
                                    // always takes the fast path, never reads it)

    // ---- W_ext slice in registers (R1 gather, 128 regs) ----
    unsigned long long W2[ROWS][4];
#pragma unroll
    for (int r = 0; r < ROWS; ++r) {
        const int gr = rbase + r;
#pragma unroll
        for (int q = 0; q < 4; ++q) {
            const int c = c0 + (q >> 1) * 128 + (q & 1) * 2;
            W2[r][q] = pk2(wext(W_res, W_in, gr, c),
                           wext(W_res, W_in, gr, c + 1));
        }
    }

    const unsigned* __restrict__ cp = &g_ctr[0];

    // prefetch x_0 for x-duty lanes
    ulonglong2 xr = make_ulonglong2(0ull, 0ull);
    if (xlane) {
        const float4 xv = __ldg((const float4*)(x) + (l - 20));
        xr.x = pk2(xv.x, xv.y);
        xr.y = pk2(xv.z, xv.w);
    }

    for (int s = 0; s < NSTEP; ++s) {
        // ---- gate: single global event, min-phase shared detection ----
        const unsigned tok = gate_wait(cp, tgt, &sflag[s & 1]);
        tgt += NCTA;

        // ---- load h: address opaquely depends on the gate token ----
        const float* buf = g_h[(s + 1) & 1];
        asm volatile("" : "+l"(buf) : "r"(tok));
        const ulonglong2 ha = __ldcg((const ulonglong2*)(buf + c0));
        ulonglong2 hb;
        if (xlane) {
            hb = xr;                        // x_s prefetched last iteration
        } else if (zlane) {
            hb.x = 0ull;  hb.y = 0ull;      // zero pad cols 2028..2047
        } else {
            hb = __ldcg((const ulonglong2*)(buf + c0 + 128));
        }
        if (xlane && s + 1 < NSTEP) {       // prefetch x_{s+1} off critical path
            const float4 xv = __ldg((const float4*)(x + (size_t)(s + 1) * XDIM) + (l - 20));
            xr.x = pk2(xv.x, xv.y);
            xr.y = pk2(xv.z, xv.w);
        }

        // ---- matvec: 16 rows x 8 cols per lane, packed f32x2 (R1 order) ----
        unsigned long long acc[ROWS];
#pragma unroll
        for (int r = 0; r < ROWS; ++r) acc[r] = mul2(W2[r][0], ha.x);
#pragma unroll
        for (int r = 0; r < ROWS; ++r) acc[r] = fma2(W2[r][1], ha.y, acc[r]);
#pragma unroll
        for (int r = 0; r < ROWS; ++r) acc[r] = fma2(W2[r][2], hb.x, acc[r]);
#pragma unroll
        for (int r = 0; r < ROWS; ++r) acc[r] = fma2(W2[r][3], hb.y, acc[r]);

        float a[ROWS];
#pragma unroll
        for (int r = 0; r < ROWS; ++r) a[r] = lo32(acc[r]) + hi32(acc[r]);

        // ---- R1-validated warp reduce-scatter (16 rows over 32 lanes) ----
        rs_stage<16, 8>(a, l);
        rs_stage<8, 4>(a, l);
        rs_stage<4, 2>(a, l);
        rs_stage<2, 1>(a, l);
        const float pv = a[0] + __shfl_xor_sync(0xffffffffu, a[0], 1);

        // parity double-buffer write (no front barrier; R11-proven)
        if ((l & 1) == 0) spart[s & 1][w][l >> 1] = pv;
        __syncthreads();                    // spart[s&1] ready for warp 0

        // ---- warp 1 lane 0: reset this parity's flag for step s+2
        //      (provably safe: s+2 pollers must first pass bar(s+1)) ----
        if (w == 1 && l == 0) sflag[s & 1] = 0u;

        // ---- warp 0: combine + tanh + publish + release-arrive ----
        if (w == 0) {
            float hv = 0.0f;
            if (l < ROWS) {
                float sum = spart[s & 1][0][l];
#pragma unroll
                for (int ww = 1; ww < 8; ++ww) sum += spart[s & 1][ww][l];
                hv = ftanh(sum);
                __stcg(&g_h[s & 1][rbase + l], hv);
            }
            __syncwarp();
            if (l == 0)
                asm volatile("red.release.gpu.global.add.u32 [%0], %1;"
                             :: "l"(g_ctr), "r"(1u) : "memory");
            // hlast after release: only out_kernel (next launch) reads it
            if (l < ROWS && (s % TSTEPS) == TSTEPS - 1)
                g_hlast[(s / TSTEPS) * RDIM + rbase + l] = hv;
        }
        // other warps proceed straight to their next-step gate
    }
}

__global__ void out_kernel(const float* __restrict__ W_out,
                           float* __restrict__ out) {
    const int b   = blockIdx.x;
    const int tid = threadIdx.x;
    const float* __restrict__ h = g_hlast + b * RDIM;

    float acc[ODIM];
#pragma unroll
    for (int o = 0; o < ODIM; ++o) acc[o] = 0.f;

    for (int k = tid; k < RDIM; k += 256) {
        const float hv = h[k];
#pragma unroll
        for (int o = 0; o < ODIM; ++o)
            acc[o] = fmaf(W_out[o * RDIM + k], hv, acc[o]);
    }
#pragma unroll
    for (int o = 0; o < ODIM; ++o) {
#pragma unroll
        for (int m = 16; m >= 1; m >>= 1)
            acc[o] += __shfl_xor_sync(0xffffffffu, acc[o], m);
    }
    __shared__ float sp[8][ODIM];
    if ((tid & 31) == 0) {
#pragma unroll
        for (int o = 0; o < ODIM; ++o) sp[tid >> 5][o] = acc[o];
    }
    __syncthreads();
    if (tid < ODIM) {
        float s2 = 0.f;
#pragma unroll
        for (int ww = 0; ww < 8; ++ww) s2 += sp[ww][tid];
        out[b * ODIM + tid] = s2;
    }
}

__global__ void reset_kernel() {   // restores state for the NEXT replay
    const int t = blockIdx.x * blockDim.x + threadIdx.x;
    if (t < 32)   g_ctr[t] = 0u;
    if (t < RDIM) g_h[1][t] = 0.0f;   // h0 = 0 (buffer read by step 0)
}

extern "C" void kernel_launch(void* const* d_in, const int* in_sizes, int n_in,
                              void* d_out, int out_size) {
    (void)in_sizes; (void)n_in; (void)out_size;
    const float* x     = (const float*)d_in[0];
    const float* W_in  = (const float*)d_in[1];
    const float* W_res = (const float*)d_in[2];
    const float* W_out = (const float*)d_in[3];
    float* out = (float*)d_out;

    // Order (rnn, out, reset): profiler lands on rnn; reset prepares the next
    // replay; first launch relies on zero-initialized device globals.
    rnn_kernel<<<NCTA, NTHREADS>>>(x, W_in, W_res);  // 125 CTAs, 1/SM
    out_kernel<<<BATCH, 256>>>(W_out, out);
    reset_kernel<<<8, 256>>>();
}

// round 14
// speedup vs baseline: 1.5085x; 1.5085x over previous
#include <cuda_runtime.h>
#include <cstdint>

#define NCTA     125
#define ROWS     16
#define NTHREADS 256         // 8 warps; warp w reads h cols [256w, 256w+256)
#define RDIM     2000
#define XDIM     28
#define TSTEPS   28
#define BATCH    512
#define NSTEP    (BATCH*TSTEPS)
#define ODIM     10
#define NGRP     8           // 8 column groups of 256 cols = 16 producer CTAs

// Static device scratch (zero-initialized; reset_kernel restores for next replay)
__device__ __align__(16) float g_h[2][2048];   // double-buffered hidden state
__device__ float    g_hlast[BATCH*RDIM];       // h at t = T-1 per batch element
__device__ unsigned g_ctr[NGRP * 32];          // per-group counters, 128B apart

// ---- packed f32x2 helpers ----
__device__ __forceinline__ unsigned long long fma2(unsigned long long a,
                                                   unsigned long long b,
                                                   unsigned long long c) {
    unsigned long long d;
    asm("fma.rn.f32x2 %0, %1, %2, %3;" : "=l"(d) : "l"(a), "l"(b), "l"(c));
    return d;
}
__device__ __forceinline__ unsigned long long mul2(unsigned long long a,
                                                   unsigned long long b) {
    unsigned long long d;
    asm("mul.rn.f32x2 %0, %1, %2;" : "=l"(d) : "l"(a), "l"(b));
    return d;
}
__device__ __forceinline__ unsigned long long pk2(float lo, float hi) {
    unsigned long long u;
    asm("mov.b64 %0, {%1, %2};" : "=l"(u)
        : "r"(__float_as_uint(lo)), "r"(__float_as_uint(hi)));
    return u;
}
__device__ __forceinline__ float lo32(unsigned long long v) { return __uint_as_float((unsigned)v); }
__device__ __forceinline__ float hi32(unsigned long long v) { return __uint_as_float((unsigned)(v >> 32)); }

// Single acquire poll load (R5/R11-proven gate; FROZEN)
__device__ __forceinline__ unsigned ld_acq(const unsigned* p) {
    unsigned v;
    asm volatile("ld.acquire.gpu.u32 %0, [%1];" : "=r"(v) : "l"(p) : "memory");
    return v;
}

// Fast tanh: (e^{2x}-1)/(e^{2x}+1) via MUFU.EX2 + MUFU.RCP.
// Abs error ~1e-7; clamp kills overflow. 1000x headroom vs the 1e-3 gate.
__device__ __forceinline__ float ftanh(float s) {
    s = fminf(fmaxf(s, -20.0f), 20.0f);
    float e;
    asm("ex2.approx.f32 %0, %1;" : "=f"(e) : "f"(s * 2.885390082f)); // 2*log2(e)*x
    float r;
    asm("rcp.approx.f32 %0, %1;" : "=f"(r) : "f"(e + 1.0f));
    return (e - 1.0f) * r;
}

// W_ext element: [W_res | W_in | 0-pad], row r, extended column c
__device__ __forceinline__ float wext(const float* __restrict__ Wres,
                                      const float* __restrict__ Win,
                                      int r, int c) {
    if (c < RDIM)        return Wres[r * RDIM + c];
    if (c < RDIM + XDIM) return Win[r * XDIM + (c - RDIM)];
    return 0.0f;
}

// R1-validated register reduce-scatter stage
template <int M, int HALF>
__device__ __forceinline__ void rs_stage(float* a, int l) {
    const bool up = (l & M) != 0;
#pragma unroll
    for (int i = 0; i < HALF; ++i) {
        float send = up ? a[i] : a[i + HALF];
        float recv = __shfl_xor_sync(0xffffffffu, send, M);
        a[i] = (up ? a[i + HALF] : a[i]) + recv;
    }
}

__global__ void __launch_bounds__(NTHREADS, 1)
rnn_kernel(const float* __restrict__ x,
           const float* __restrict__ W_in,
           const float* __restrict__ W_res) {
    // Transposed partials: spart[parity][row][warp], padded to 12 floats so
    // the publisher reads each row as two conflict-free LDS.128.
    __shared__ __align__(16) float spart[2][ROWS][12];

    const int tid   = threadIdx.x;
    const int w     = tid >> 5;
    const int l     = tid & 31;
    const int rbase = blockIdx.x * ROWS;
    const int c0    = w * 256 + l * 4;          // lane's column base (R1 layout)
    const unsigned ng = (w < 7) ? 16u : 13u;    // producers in this warp's group
    unsigned tgt = 0u;                           // poll target = s * ng

    const bool xlane = (w == 7) && (l >= 20) && (l < 27);  // cols 2000..2027 <- x
    const bool zlane = (w == 7) && (l >= 27);              // cols 2028..2047 <- 0

    // ---- W_ext slice in registers (R1 gather, 128 regs) ----
    unsigned long long W2[ROWS][4];
#pragma unroll
    for (int r = 0; r < ROWS; ++r) {
        const int gr = rbase + r;
#pragma unroll
        for (int q = 0; q < 4; ++q) {
            const int c = c0 + (q >> 1) * 128 + (q & 1) * 2;
            W2[r][q] = pk2(wext(W_res, W_in, gr, c),
                           wext(W_res, W_in, gr, c + 1));
        }
    }

    const unsigned* __restrict__ cp = &g_ctr[w * 32];
    unsigned* __restrict__ ap = &g_ctr[(blockIdx.x >> 4) * 32];

    // prefetch x_0 for x-duty lanes
    ulonglong2 xr = make_ulonglong2(0ull, 0ull);
    if (xlane) {
        const float4 xv = __ldg((const float4*)(x) + (l - 20));
        xr.x = pk2(xv.x, xv.y);
        xr.y = pk2(xv.z, xv.w);
    }

    for (int s = 0; s < NSTEP; ++s) {
        // ---- per-warp gate (FROZEN R11 protocol) ----
        while (ld_acq(cp) < tgt) { }
        tgt += ng;

        // ---- load this lane's 8 h-columns straight into registers ----
        const float* __restrict__ buf = g_h[(s + 1) & 1];
        const ulonglong2 ha = __ldcg((const ulonglong2*)(buf + c0));
        ulonglong2 hb;
        if (xlane) {
            hb = xr;                        // x_s prefetched last iteration
        } else if (zlane) {
            hb.x = 0ull;  hb.y = 0ull;      // zero pad cols 2028..2047
        } else {
            hb = __ldcg((const ulonglong2*)(buf + c0 + 128));
        }
        if (xlane && s + 1 < NSTEP) {       // prefetch x_{s+1} off critical path
            const float4 xv = __ldg((const float4*)(x + (size_t)(s + 1) * XDIM) + (l - 20));
            xr.x = pk2(xv.x, xv.y);
            xr.y = pk2(xv.z, xv.w);
        }

        // ---- matvec: 16 rows x 8 cols per lane, packed f32x2 (R1 order) ----
        unsigned long long acc[ROWS];
#pragma unroll
        for (int r = 0; r < ROWS; ++r) acc[r] = mul2(W2[r][0], ha.x);
#pragma unroll
        for (int r = 0; r < ROWS; ++r) acc[r] = fma2(W2[r][1], ha.y, acc[r]);
#pragma unroll
        for (int r = 0; r < ROWS; ++r) acc[r] = fma2(W2[r][2], hb.x, acc[r]);
#pragma unroll
        for (int r = 0; r < ROWS; ++r) acc[r] = fma2(W2[r][3], hb.y, acc[r]);

        float a[ROWS];
#pragma unroll
        for (int r = 0; r < ROWS; ++r) a[r] = lo32(acc[r]) + hi32(acc[r]);

        // ---- R1-validated warp reduce-scatter (16 rows over 32 lanes) ----
        rs_stage<16, 8>(a, l);
        rs_stage<8, 4>(a, l);
        rs_stage<4, 2>(a, l);
        rs_stage<2, 1>(a, l);
        const float pv = a[0] + __shfl_xor_sync(0xffffffffu, a[0], 1);

        // parity double-buffer write (no front barrier; R11-proven)
        if ((l & 1) == 0) spart[s & 1][l >> 1][w] = pv;

        // ---- split barrier: non-publishers arrive and run ahead to their
        //      next gate; only warp 0 waits. Parity-indexed named barriers
        //      keep run-ahead arrivals (bounded to 1 step) separated. ----
        const int bid = 1 + (s & 1);
        if (w != 0) {
            asm volatile("bar.arrive %0, %1;" :: "r"(bid), "r"(NTHREADS) : "memory");
            continue;   // straight to next-step poll: earlier sampling phase
        }
        asm volatile("bar.sync %0, %1;" :: "r"(bid), "r"(NTHREADS) : "memory");

        // ---- warp 0: combine (LDS.128 x2) + tanh + publish + release ----
        {
            float hv = 0.0f;
            if (l < ROWS) {
                const float4 p0 = *(const float4*)&spart[s & 1][l][0];
                const float4 p1 = *(const float4*)&spart[s & 1][l][4];
                const float sum = ((p0.x + p0.y) + (p0.z + p0.w))
                                + ((p1.x + p1.y) + (p1.z + p1.w));
                hv = ftanh(sum);
                __stcg(&g_h[s & 1][rbase + l], hv);
            }
            __syncwarp();
            if (l == 0)
                asm volatile("red.release.gpu.global.add.u32 [%0], %1;"
                             :: "l"(ap), "r"(1u) : "memory");
            // hlast after release: only out_kernel (next launch) reads it
            if (l < ROWS && (s % TSTEPS) == TSTEPS - 1)
                g_hlast[(s / TSTEPS) * RDIM + rbase + l] = hv;
        }
    }
}

__global__ void out_kernel(const float* __restrict__ W_out,
                           float* __restrict__ out) {
    const int b   = blockIdx.x;
    const int tid = threadIdx.x;
    const float* __restrict__ h = g_hlast + b * RDIM;

    float acc[ODIM];
#pragma unroll
    for (int o = 0; o < ODIM; ++o) acc[o] = 0.f;

    for (int k = tid; k < RDIM; k += 256) {
        const float hv = h[k];
#pragma unroll
        for (int o = 0; o < ODIM; ++o)
            acc[o] = fmaf(W_out[o * RDIM + k], hv, acc[o]);
    }
#pragma unroll
    for (int o = 0; o < ODIM; ++o) {
#pragma unroll
        for (int m = 16; m >= 1; m >>= 1)
            acc[o] += __shfl_xor_sync(0xffffffffu, acc[o], m);
    }
    __shared__ float sp[8][ODIM];
    if ((tid & 31) == 0) {
#pragma unroll
        for (int o = 0; o < ODIM; ++o) sp[tid >> 5][o] = acc[o];
    }
    __syncthreads();
    if (tid < ODIM) {
        float s2 = 0.f;
#pragma unroll
        for (int ww = 0; ww < 8; ++ww) s2 += sp[ww][tid];
        out[b * ODIM + tid] = s2;
    }
}

__global__ void reset_kernel() {   // restores state for the NEXT replay
    const int t = blockIdx.x * blockDim.x + threadIdx.x;
    if (t < NGRP * 32) g_ctr[t] = 0u;
    if (t < RDIM)      g_h[1][t] = 0.0f;   // h0 = 0 (buffer read by step 0)
}

extern "C" void kernel_launch(void* const* d_in, const int* in_sizes, int n_in,
                              void* d_out, int out_size) {
    (void)in_sizes; (void)n_in; (void)out_size;
    const float* x     = (const float*)d_in[0];
    const float* W_in  = (const float*)d_in[1];
    const float* W_res = (const float*)d_in[2];
    const float* W_out = (const float*)d_in[3];
    float* out = (float*)d_out;

    // Order (rnn, out, reset): profiler lands on rnn; reset prepares the next
    // replay; first launch relies on zero-initialized device globals.
    rnn_kernel<<<NCTA, NTHREADS>>>(x, W_in, W_res);  // 125 CTAs, 1/SM
    out_kernel<<<BATCH, 256>>>(W_out, out);
    reset_kernel<<<8, 256>>>();
}